// round 16
// baseline (speedup 1.0000x reference)
#include <cuda_runtime.h>
#include <cuda_bf16.h>
#include <math.h>
#include <cstdint>

#define B_  4
#define S_  2048
#define D_  1024
#define H_  16
#define DK_ 64
#define NTOK (B_ * S_)          // 8192
#define SBH  (B_ * H_)          // 64

// ---------------- scratch (static device globals; no allocs) ----------------
__device__ float g_Q[(size_t)NTOK * D_];
__device__ float g_K[(size_t)NTOK * D_];
__device__ float g_cos[S_ * 32];
__device__ float g_sin[S_ * 32];
__device__ __nv_bfloat16 g_xhi[(size_t)NTOK * D_];
__device__ __nv_bfloat16 g_xlo[(size_t)NTOK * D_];
__device__ __nv_bfloat16 g_Ahi[(size_t)NTOK * D_];
__device__ __nv_bfloat16 g_Alo[(size_t)NTOK * D_];
__device__ __nv_bfloat16 g_Whi[4 * 1024 * 1024];
__device__ __nv_bfloat16 g_Wlo[4 * 1024 * 1024];
__device__ __nv_bfloat16 g_Qh[(size_t)NTOK * D_];
__device__ __nv_bfloat16 g_Ql[(size_t)NTOK * D_];
__device__ __nv_bfloat16 g_Kh[(size_t)NTOK * D_];
__device__ __nv_bfloat16 g_Kl[(size_t)NTOK * D_];
__device__ __nv_bfloat16 g_Vh[(size_t)NTOK * D_];
__device__ __nv_bfloat16 g_Vl[(size_t)NTOK * D_];

// ---------------- warp-level MMA helpers (sm_80 baseline) -------------------
__device__ __forceinline__ void ldsm4(uint32_t* r, uint32_t addr) {
    asm volatile(
        "ldmatrix.sync.aligned.m8n8.x4.shared.b16 {%0,%1,%2,%3}, [%4];"
        : "=r"(r[0]), "=r"(r[1]), "=r"(r[2]), "=r"(r[3]) : "r"(addr));
}
__device__ __forceinline__ void ldsm4t(uint32_t* r, uint32_t addr) {
    asm volatile(
        "ldmatrix.sync.aligned.m8n8.x4.trans.shared.b16 {%0,%1,%2,%3}, [%4];"
        : "=r"(r[0]), "=r"(r[1]), "=r"(r[2]), "=r"(r[3]) : "r"(addr));
}
__device__ __forceinline__ void mma16816(float* c, const uint32_t* a,
                                         const uint32_t* b) {
    asm volatile(
        "mma.sync.aligned.m16n8k16.row.col.f32.bf16.bf16.f32 "
        "{%0,%1,%2,%3}, {%4,%5,%6,%7}, {%8,%9}, {%0,%1,%2,%3};"
        : "+f"(c[0]), "+f"(c[1]), "+f"(c[2]), "+f"(c[3])
        : "r"(a[0]), "r"(a[1]), "r"(a[2]), "r"(a[3]), "r"(b[0]), "r"(b[1]));
}
__device__ __forceinline__ uint32_t smem_u32(const void* p) {
    uint32_t a;
    asm("{ .reg .u64 t; cvta.to.shared.u64 t, %1; cvt.u32.u64 %0, t; }"
        : "=r"(a) : "l"(p));
    return a;
}
__device__ __forceinline__ void split2(float a, float b, uint32_t& hi,
                                       uint32_t& lo) {
    __nv_bfloat16 ha = __float2bfloat16(a), hb = __float2bfloat16(b);
    __nv_bfloat16 la = __float2bfloat16(a - __bfloat162float(ha));
    __nv_bfloat16 lb = __float2bfloat16(b - __bfloat162float(hb));
    __nv_bfloat162 Hh; Hh.x = ha; Hh.y = hb;
    __nv_bfloat162 Ll; Ll.x = la; Ll.y = lb;
    hi = *(uint32_t*)&Hh;
    lo = *(uint32_t*)&Ll;
}

// ---------------- split fp32 -> (hi, lo) bf16 (x and weights only) ----------
// dsel: 0=x, 1..4=W[dsel-1]
__global__ __launch_bounds__(256) void split_k(const float* src, int dsel,
                                               int n4) {
    int i = blockIdx.x * 256 + threadIdx.x;
    if (i >= n4) return;
    __nv_bfloat16 *hi, *lo;
    if (dsel == 0) { hi = g_xhi; lo = g_xlo; }
    else {
        hi = g_Whi + (size_t)(dsel - 1) * 1048576;
        lo = g_Wlo + (size_t)(dsel - 1) * 1048576;
    }
    float4 v = *(const float4*)(src + 4 * (size_t)i);
    float vv[4] = {v.x, v.y, v.z, v.w};
    __nv_bfloat16 h[4], l[4];
#pragma unroll
    for (int j = 0; j < 4; ++j) {
        h[j] = __float2bfloat16(vv[j]);
        l[j] = __float2bfloat16(vv[j] - __bfloat162float(h[j]));
    }
    *(uint2*)(hi + 4 * (size_t)i) = *(uint2*)h;
    *(uint2*)(lo + 4 * (size_t)i) = *(uint2*)l;
}

// ---------------- HMMA split-bf16 GEMM: C = A @ W^T (round-10 verified) ----
// 128x128 tile/CTA, BK=32, 8 warps (2m x 4n), single-buffer smem stride 40.
// csel/z: 0 -> g_Q fp32, 1 -> g_K fp32, 2 -> split bf16 V, 3 -> Cout fp32.
#define GST 40   // smem row stride in bf16

__global__ __launch_bounds__(256) void gemm_mma(int asel, int wsel, int csel,
                                                float* Cout) {
    __shared__ __nv_bfloat16 sAh[128 * GST];
    __shared__ __nv_bfloat16 sAl[128 * GST];
    __shared__ __nv_bfloat16 sWh[128 * GST];
    __shared__ __nv_bfloat16 sWl[128 * GST];

    const int tid = threadIdx.x, wid = tid >> 5, lid = tid & 31;
    const int wr = wid & 1, wc = wid >> 1;
    const int m0 = blockIdx.y * 128, n0 = blockIdx.x * 128;
    const int ws = (wsel < 0) ? (int)blockIdx.z : wsel;
    const int cs = (csel < 0) ? (int)blockIdx.z : csel;

    const __nv_bfloat16* Ah = asel ? g_Ahi : g_xhi;
    const __nv_bfloat16* Al = asel ? g_Alo : g_xlo;
    const __nv_bfloat16* Wh = g_Whi + (size_t)ws * 1048576;
    const __nv_bfloat16* Wl = g_Wlo + (size_t)ws * 1048576;

    const uint32_t bAh = smem_u32(sAh), bAl = smem_u32(sAl);
    const uint32_t bWh = smem_u32(sWh), bWl = smem_u32(sWl);

    const int rowSelA = wr * 64 + (lid & 15);
    const int kSelA   = (lid >> 4) * 8;
    const int rowSelW = wc * 32 + ((lid >> 4) * 8) + (lid & 7);
    const int kSelW   = ((lid >> 3) & 1) * 8;

    float acc[4][4][4];
#pragma unroll
    for (int i = 0; i < 4; ++i)
#pragma unroll
        for (int j = 0; j < 4; ++j)
#pragma unroll
            for (int t = 0; t < 4; ++t) acc[i][j][t] = 0.f;

    for (int k0 = 0; k0 < 1024; k0 += 32) {
        __syncthreads();
#pragma unroll
        for (int p = 0; p < 2; ++p) {
            int c = tid + p * 256;
            int row = c >> 2, kc = (c & 3) * 8;
            int so = row * GST + kc;
            size_t ao = (size_t)(m0 + row) * 1024 + k0 + kc;
            size_t wo = (size_t)(n0 + row) * 1024 + k0 + kc;
            *(uint4*)(sAh + so) = *(const uint4*)(Ah + ao);
            *(uint4*)(sAl + so) = *(const uint4*)(Al + ao);
            *(uint4*)(sWh + so) = *(const uint4*)(Wh + wo);
            *(uint4*)(sWl + so) = *(const uint4*)(Wl + wo);
        }
        __syncthreads();

#pragma unroll
        for (int ks = 0; ks < 2; ++ks) {
            uint32_t bh[4][2], bl[4][2];
#pragma unroll
            for (int nt16 = 0; nt16 < 2; ++nt16) {
                uint32_t r[4];
                uint32_t off =
                    (uint32_t)((rowSelW + nt16 * 16) * GST + ks * 16 + kSelW) * 2;
                ldsm4(r, bWh + off);
                bh[nt16 * 2][0] = r[0]; bh[nt16 * 2][1] = r[1];
                bh[nt16 * 2 + 1][0] = r[2]; bh[nt16 * 2 + 1][1] = r[3];
                ldsm4(r, bWl + off);
                bl[nt16 * 2][0] = r[0]; bl[nt16 * 2][1] = r[1];
                bl[nt16 * 2 + 1][0] = r[2]; bl[nt16 * 2 + 1][1] = r[3];
            }
            uint32_t a[4][4];
#pragma unroll
            for (int mt = 0; mt < 4; ++mt)
                ldsm4(a[mt],
                      bAh + (uint32_t)((rowSelA + mt * 16) * GST + ks * 16 + kSelA) * 2);
#pragma unroll
            for (int mt = 0; mt < 4; ++mt)
#pragma unroll
                for (int nt = 0; nt < 4; ++nt) {
                    mma16816(acc[mt][nt], a[mt], bh[nt]);
                    mma16816(acc[mt][nt], a[mt], bl[nt]);
                }
#pragma unroll
            for (int mt = 0; mt < 4; ++mt)
                ldsm4(a[mt],
                      bAl + (uint32_t)((rowSelA + mt * 16) * GST + ks * 16 + kSelA) * 2);
#pragma unroll
            for (int mt = 0; mt < 4; ++mt)
#pragma unroll
                for (int nt = 0; nt < 4; ++nt)
                    mma16816(acc[mt][nt], a[mt], bh[nt]);
        }
    }

    const int g = lid >> 2, j2 = (lid & 3) * 2;
    if (cs == 2) {
        // V: write split bf16 directly (feeds flash, skips V split pass).
#pragma unroll
        for (int mt = 0; mt < 4; ++mt) {
            int row = m0 + wr * 64 + mt * 16 + g;
#pragma unroll
            for (int nt = 0; nt < 4; ++nt) {
                int col = n0 + wc * 32 + nt * 8 + j2;
                uint32_t hi, lo;
                split2(acc[mt][nt][0], acc[mt][nt][1], hi, lo);
                *(uint32_t*)(g_Vh + (size_t)row * 1024 + col) = hi;
                *(uint32_t*)(g_Vl + (size_t)row * 1024 + col) = lo;
                split2(acc[mt][nt][2], acc[mt][nt][3], hi, lo);
                *(uint32_t*)(g_Vh + (size_t)(row + 8) * 1024 + col) = hi;
                *(uint32_t*)(g_Vl + (size_t)(row + 8) * 1024 + col) = lo;
            }
        }
    } else {
        float* C = (cs == 0) ? g_Q : (cs == 1) ? g_K : Cout;
#pragma unroll
        for (int mt = 0; mt < 4; ++mt) {
            int row = m0 + wr * 64 + mt * 16 + g;
#pragma unroll
            for (int nt = 0; nt < 4; ++nt) {
                int col = n0 + wc * 32 + nt * 8 + j2;
                *(float2*)&C[(size_t)row * 1024 + col] =
                    make_float2(acc[mt][nt][0], acc[mt][nt][1]);
                *(float2*)&C[(size_t)(row + 8) * 1024 + col] =
                    make_float2(acc[mt][nt][2], acc[mt][nt][3]);
            }
        }
    }
}

// ---------------- RoPE trig table (VERIFIED recipe: pow + cos/sin) ----------
// DO NOT switch to exp2/remainder/sincosf — that recipe failed 3/3 times
// with the 0.8156 degenerate-scores signature (rounds 3, 4, 15).
__global__ __launch_bounds__(256) void build_trig(const int* __restrict__ pos) {
    int idx = blockIdx.x * blockDim.x + threadIdx.x;
    if (idx >= S_ * 32) return;
    int s = idx >> 5;
    int i = idx & 31;
    double inv = pow(10000.0, -(double)(2 * i) / 64.0);
    double ang = (double)pos[s] * inv;
    g_cos[idx] = (float)cos(ang);
    g_sin[idx] = (float)sin(ang);
}

// ---------------- RoPE apply: fp32 Q/K -> rotated split bf16 ----------------
// Q scaled by 1/8 (softmax scale folded).
__global__ __launch_bounds__(256) void rope_apply() {
    int idx = blockIdx.x * blockDim.x + threadIdx.x;
    if (idx >= NTOK * (D_ / 2)) return;
    int i   = idx & 31;
    int r   = idx >> 5;
    int h   = r & 15;
    int tok = r >> 4;
    int s   = tok & (S_ - 1);
    float c  = g_cos[(s << 5) + i];
    float sn = g_sin[(s << 5) + i];
    size_t base = (size_t)tok * D_ + (size_t)h * DK_ + 2 * i;

    float2 q = *(float2*)&g_Q[base];
    float qx = (q.x * c - q.y * sn) * 0.125f;
    float qy = (q.x * sn + q.y * c) * 0.125f;
    uint32_t hi, lo;
    split2(qx, qy, hi, lo);
    *(uint32_t*)(g_Qh + base) = hi;
    *(uint32_t*)(g_Ql + base) = lo;

    float2 k = *(float2*)&g_K[base];
    float kx = k.x * c - k.y * sn;
    float ky = k.x * sn + k.y * c;
    split2(kx, ky, hi, lo);
    *(uint32_t*)(g_Kh + base) = hi;
    *(uint32_t*)(g_Kl + base) = lo;
}

// ---------------- fused flash attention (HMMA, split-bf16) ------------------
#define GSTF 72  // smem row stride (bf16)

__global__ __launch_bounds__(256) void flash_mma() {
    __shared__ __nv_bfloat16 sKh[64 * GSTF];
    __shared__ __nv_bfloat16 sKl[64 * GSTF];
    __shared__ __nv_bfloat16 sVh[64 * GSTF];
    __shared__ __nv_bfloat16 sVl[64 * GSTF];

    const int tid = threadIdx.x, wid = tid >> 5, lid = tid & 31;
    const int qt = 15 - (int)blockIdx.x;
    const int bh = blockIdx.y;
    const int b = bh >> 4, h = bh & 15;
    const size_t base = (size_t)b * S_ * D_ + (size_t)h * DK_;
    const int q0 = qt * 128;
    const int g = lid >> 2, j2 = (lid & 3) * 2;
    const int qrow0 = q0 + wid * 16 + g;

    uint32_t qh[4][4], ql[4][4];
#pragma unroll
    for (int ks = 0; ks < 4; ++ks) {
        size_t r0 = base + (size_t)qrow0 * D_ + ks * 16 + j2;
        size_t r1 = base + (size_t)(qrow0 + 8) * D_ + ks * 16 + j2;
        qh[ks][0] = *(const uint32_t*)(g_Qh + r0);
        qh[ks][1] = *(const uint32_t*)(g_Qh + r1);
        qh[ks][2] = *(const uint32_t*)(g_Qh + r0 + 8);
        qh[ks][3] = *(const uint32_t*)(g_Qh + r1 + 8);
        ql[ks][0] = *(const uint32_t*)(g_Ql + r0);
        ql[ks][1] = *(const uint32_t*)(g_Ql + r1);
        ql[ks][2] = *(const uint32_t*)(g_Ql + r0 + 8);
        ql[ks][3] = *(const uint32_t*)(g_Ql + r1 + 8);
    }

    float o[8][4];
#pragma unroll
    for (int nt = 0; nt < 8; ++nt)
#pragma unroll
        for (int t = 0; t < 4; ++t) o[nt][t] = 0.f;
    float m0 = -1e30f, m1 = -1e30f, l0 = 0.f, l1 = 0.f;

    const uint32_t bKh = smem_u32(sKh), bKl = smem_u32(sKl);
    const uint32_t bVh = smem_u32(sVh), bVl = smem_u32(sVl);
    const uint32_t selK =
        (uint32_t)((((lid >> 4) * 8) + (lid & 7)) * GSTF + ((lid >> 3) & 1) * 8) * 2;
    const uint32_t selV =
        (uint32_t)(((((lid >> 3) & 1) * 8) + (lid & 7)) * GSTF + (lid >> 4) * 8) * 2;

    const int nkt = 2 * qt + 2;
    for (int kt = 0; kt < nkt; ++kt) {
        const int k0 = kt * 64;
        __syncthreads();
#pragma unroll
        for (int p = 0; p < 2; ++p) {
            int c = tid + p * 256;
            int row = c >> 3, col8 = (c & 7) * 8;
            size_t go = base + (size_t)(k0 + row) * D_ + col8;
            int so = row * GSTF + col8;
            *(uint4*)(sKh + so) = *(const uint4*)(g_Kh + go);
            *(uint4*)(sKl + so) = *(const uint4*)(g_Kl + go);
            *(uint4*)(sVh + so) = *(const uint4*)(g_Vh + go);
            *(uint4*)(sVl + so) = *(const uint4*)(g_Vl + go);
        }
        __syncthreads();

        float s[8][4];
#pragma unroll
        for (int nt = 0; nt < 8; ++nt)
#pragma unroll
            for (int t = 0; t < 4; ++t) s[nt][t] = 0.f;

#pragma unroll
        for (int ks = 0; ks < 4; ++ks) {
            uint32_t kbh[8][2], kbl[8][2], r[4];
#pragma unroll
            for (int n16 = 0; n16 < 4; ++n16) {
                uint32_t off = selK + (uint32_t)((n16 * 16) * GSTF + ks * 16) * 2;
                ldsm4(r, bKh + off);
                kbh[2 * n16][0] = r[0]; kbh[2 * n16][1] = r[1];
                kbh[2 * n16 + 1][0] = r[2]; kbh[2 * n16 + 1][1] = r[3];
                ldsm4(r, bKl + off);
                kbl[2 * n16][0] = r[0]; kbl[2 * n16][1] = r[1];
                kbl[2 * n16 + 1][0] = r[2]; kbl[2 * n16 + 1][1] = r[3];
            }
#pragma unroll
            for (int nt = 0; nt < 8; ++nt) {
                mma16816(s[nt], qh[ks], kbh[nt]);
                mma16816(s[nt], ql[ks], kbh[nt]);
                mma16816(s[nt], qh[ks], kbl[nt]);
            }
        }

        if (k0 + 63 > q0 + wid * 16) {
#pragma unroll
            for (int nt = 0; nt < 8; ++nt) {
                int key = k0 + nt * 8 + j2;
                if (key > qrow0)         s[nt][0] = -1e30f;
                if (key + 1 > qrow0)     s[nt][1] = -1e30f;
                if (key > qrow0 + 8)     s[nt][2] = -1e30f;
                if (key + 1 > qrow0 + 8) s[nt][3] = -1e30f;
            }
        }

        float mx0 = -1e30f, mx1 = -1e30f;
#pragma unroll
        for (int nt = 0; nt < 8; ++nt) {
            mx0 = fmaxf(mx0, fmaxf(s[nt][0], s[nt][1]));
            mx1 = fmaxf(mx1, fmaxf(s[nt][2], s[nt][3]));
        }
        mx0 = fmaxf(mx0, __shfl_xor_sync(0xffffffffu, mx0, 1));
        mx0 = fmaxf(mx0, __shfl_xor_sync(0xffffffffu, mx0, 2));
        mx1 = fmaxf(mx1, __shfl_xor_sync(0xffffffffu, mx1, 1));
        mx1 = fmaxf(mx1, __shfl_xor_sync(0xffffffffu, mx1, 2));
        float mn0 = fmaxf(m0, mx0), mn1 = fmaxf(m1, mx1);
        float a0 = __expf(m0 - mn0), a1 = __expf(m1 - mn1);
        float sum0 = 0.f, sum1 = 0.f;
#pragma unroll
        for (int nt = 0; nt < 8; ++nt) {
            s[nt][0] = __expf(s[nt][0] - mn0);
            s[nt][1] = __expf(s[nt][1] - mn0);
            s[nt][2] = __expf(s[nt][2] - mn1);
            s[nt][3] = __expf(s[nt][3] - mn1);
            sum0 += s[nt][0] + s[nt][1];
            sum1 += s[nt][2] + s[nt][3];
        }
        sum0 += __shfl_xor_sync(0xffffffffu, sum0, 1);
        sum0 += __shfl_xor_sync(0xffffffffu, sum0, 2);
        sum1 += __shfl_xor_sync(0xffffffffu, sum1, 1);
        sum1 += __shfl_xor_sync(0xffffffffu, sum1, 2);
        l0 = l0 * a0 + sum0;
        l1 = l1 * a1 + sum1;
        m0 = mn0; m1 = mn1;
#pragma unroll
        for (int nt = 0; nt < 8; ++nt) {
            o[nt][0] *= a0; o[nt][1] *= a0;
            o[nt][2] *= a1; o[nt][3] *= a1;
        }

#pragma unroll
        for (int ks = 0; ks < 4; ++ks) {
            uint32_t ph[4], pl[4];
            split2(s[2 * ks][0], s[2 * ks][1], ph[0], pl[0]);
            split2(s[2 * ks][2], s[2 * ks][3], ph[1], pl[1]);
            split2(s[2 * ks + 1][0], s[2 * ks + 1][1], ph[2], pl[2]);
            split2(s[2 * ks + 1][2], s[2 * ks + 1][3], ph[3], pl[3]);

            uint32_t vbh[8][2], vbl[8][2], r[4];
#pragma unroll
            for (int n16 = 0; n16 < 4; ++n16) {
                uint32_t off = selV + (uint32_t)((ks * 16) * GSTF + n16 * 16) * 2;
                ldsm4t(r, bVh + off);
                vbh[2 * n16][0] = r[0]; vbh[2 * n16][1] = r[1];
                vbh[2 * n16 + 1][0] = r[2]; vbh[2 * n16 + 1][1] = r[3];
                ldsm4t(r, bVl + off);
                vbl[2 * n16][0] = r[0]; vbl[2 * n16][1] = r[1];
                vbl[2 * n16 + 1][0] = r[2]; vbl[2 * n16 + 1][1] = r[3];
            }
#pragma unroll
            for (int nt = 0; nt < 8; ++nt) {
                mma16816(o[nt], ph, vbh[nt]);
                mma16816(o[nt], pl, vbh[nt]);
                mma16816(o[nt], ph, vbl[nt]);
            }
        }
    }

    // Epilogue: normalize and write SPLIT bf16 directly to g_Ahi/g_Alo.
    const float i0 = 1.f / l0, i1 = 1.f / l1;
#pragma unroll
    for (int nt = 0; nt < 8; ++nt) {
        size_t r0 = base + (size_t)qrow0 * D_ + nt * 8 + j2;
        size_t r1 = base + (size_t)(qrow0 + 8) * D_ + nt * 8 + j2;
        uint32_t hi, lo;
        split2(o[nt][0] * i0, o[nt][1] * i0, hi, lo);
        *(uint32_t*)(g_Ahi + r0) = hi;
        *(uint32_t*)(g_Alo + r0) = lo;
        split2(o[nt][2] * i1, o[nt][3] * i1, hi, lo);
        *(uint32_t*)(g_Ahi + r1) = hi;
        *(uint32_t*)(g_Alo + r1) = lo;
    }
}

// ---------------- launch -----------------------------------------------------
extern "C" void kernel_launch(void* const* d_in, const int* in_sizes, int n_in,
                              void* d_out, int out_size) {
    int ix = 0, ipos = 1;
    int iw[4] = {2, 3, 4, 5};
    {
        int nw = 0, found_x = 0, found_p = 0, tmp[8];
        for (int i = 0; i < n_in && i < 8; ++i) {
            if (in_sizes[i] == S_) { ipos = i; found_p = 1; }
            else if (in_sizes[i] == NTOK * D_) { ix = i; found_x = 1; }
            else if (nw < 8) tmp[nw++] = i;
        }
        if (found_x && found_p && nw >= 4) {
            iw[0] = tmp[0]; iw[1] = tmp[1]; iw[2] = tmp[2]; iw[3] = tmp[3];
        }
    }

    const float* x  = (const float*)d_in[ix];
    const int* pos  = (const int*)d_in[ipos];
    const float* Wq = (const float*)d_in[iw[0]];
    const float* Wk = (const float*)d_in[iw[1]];
    const float* Wv = (const float*)d_in[iw[2]];
    const float* Wo = (const float*)d_in[iw[3]];
    float* out = (float*)d_out;

    const int nT = NTOK * D_ / 4;
    const int nW = 1048576 / 4;

    split_k<<<(nT + 255) / 256, 256>>>(x, 0, nT);
    split_k<<<(nW + 255) / 256, 256>>>(Wq, 1, nW);
    split_k<<<(nW + 255) / 256, 256>>>(Wk, 2, nW);
    split_k<<<(nW + 255) / 256, 256>>>(Wv, 3, nW);
    split_k<<<(nW + 255) / 256, 256>>>(Wo, 4, nW);

    // QKV projections in one launch; V writes split bf16 directly.
    dim3 gqkv(D_ / 128, NTOK / 128, 3);
    gemm_mma<<<gqkv, 256>>>(0, -1, -1, nullptr);

    build_trig<<<(S_ * 32 + 255) / 256, 256>>>(pos);
    rope_apply<<<(NTOK * (D_ / 2) + 255) / 256, 256>>>();  // -> Qh/Ql/Kh/Kl

    dim3 fg(S_ / 128, SBH);
    flash_mma<<<fg, 256>>>();                               // -> Ahi/Alo

    dim3 go(D_ / 128, NTOK / 128, 1);
    gemm_mma<<<go, 256>>>(1, 3, 3, out);
}

// round 17
// speedup vs baseline: 1.8305x; 1.8305x over previous
#include <cuda_runtime.h>
#include <cuda_bf16.h>
#include <math.h>
#include <cstdint>

#define B_  4
#define S_  2048
#define D_  1024
#define H_  16
#define DK_ 64
#define NTOK (B_ * S_)          // 8192
#define SBH  (B_ * H_)          // 64

// ---------------- scratch (static device globals; no allocs) ----------------
__device__ float g_Q[(size_t)NTOK * D_];
__device__ float g_K[(size_t)NTOK * D_];
__device__ float g_V[(size_t)NTOK * D_];
__device__ float g_cos[S_ * 32];
__device__ float g_sin[S_ * 32];
__device__ __nv_bfloat16 g_xhi[(size_t)NTOK * D_];
__device__ __nv_bfloat16 g_xlo[(size_t)NTOK * D_];
__device__ __nv_bfloat16 g_Ahi[(size_t)NTOK * D_];
__device__ __nv_bfloat16 g_Alo[(size_t)NTOK * D_];
__device__ __nv_bfloat16 g_Whi[4 * 1024 * 1024];
__device__ __nv_bfloat16 g_Wlo[4 * 1024 * 1024];
__device__ __nv_bfloat16 g_Qh[(size_t)NTOK * D_];
__device__ __nv_bfloat16 g_Ql[(size_t)NTOK * D_];
__device__ __nv_bfloat16 g_Kh[(size_t)NTOK * D_];
__device__ __nv_bfloat16 g_Kl[(size_t)NTOK * D_];
__device__ __nv_bfloat16 g_Vh[(size_t)NTOK * D_];
__device__ __nv_bfloat16 g_Vl[(size_t)NTOK * D_];

// ---------------- warp-level MMA helpers (sm_80 baseline) -------------------
__device__ __forceinline__ void ldsm4(uint32_t* r, uint32_t addr) {
    asm volatile(
        "ldmatrix.sync.aligned.m8n8.x4.shared.b16 {%0,%1,%2,%3}, [%4];"
        : "=r"(r[0]), "=r"(r[1]), "=r"(r[2]), "=r"(r[3]) : "r"(addr));
}
__device__ __forceinline__ void ldsm4t(uint32_t* r, uint32_t addr) {
    asm volatile(
        "ldmatrix.sync.aligned.m8n8.x4.trans.shared.b16 {%0,%1,%2,%3}, [%4];"
        : "=r"(r[0]), "=r"(r[1]), "=r"(r[2]), "=r"(r[3]) : "r"(addr));
}
__device__ __forceinline__ void mma16816(float* c, const uint32_t* a,
                                         const uint32_t* b) {
    asm volatile(
        "mma.sync.aligned.m16n8k16.row.col.f32.bf16.bf16.f32 "
        "{%0,%1,%2,%3}, {%4,%5,%6,%7}, {%8,%9}, {%0,%1,%2,%3};"
        : "+f"(c[0]), "+f"(c[1]), "+f"(c[2]), "+f"(c[3])
        : "r"(a[0]), "r"(a[1]), "r"(a[2]), "r"(a[3]), "r"(b[0]), "r"(b[1]));
}
__device__ __forceinline__ uint32_t smem_u32(const void* p) {
    uint32_t a;
    asm("{ .reg .u64 t; cvta.to.shared.u64 t, %1; cvt.u32.u64 %0, t; }"
        : "=r"(a) : "l"(p));
    return a;
}
__device__ __forceinline__ void split2(float a, float b, uint32_t& hi,
                                       uint32_t& lo) {
    __nv_bfloat16 ha = __float2bfloat16(a), hb = __float2bfloat16(b);
    __nv_bfloat16 la = __float2bfloat16(a - __bfloat162float(ha));
    __nv_bfloat16 lb = __float2bfloat16(b - __bfloat162float(hb));
    __nv_bfloat162 Hh; Hh.x = ha; Hh.y = hb;
    __nv_bfloat162 Ll; Ll.x = la; Ll.y = lb;
    hi = *(uint32_t*)&Hh;
    lo = *(uint32_t*)&Ll;
}

// ---------------- split fp32 -> (hi, lo) bf16 --------------------------------
// ssel: 0 = param src, 1 = g_V. dsel: 0=x, 1..4=W[dsel-1], 8=V.
__global__ __launch_bounds__(256) void split_k(const float* src, int ssel,
                                               int dsel, int n4) {
    int i = blockIdx.x * 256 + threadIdx.x;
    if (i >= n4) return;
    const float* s = (ssel == 0) ? src : g_V;
    __nv_bfloat16 *hi, *lo;
    if (dsel == 0) { hi = g_xhi; lo = g_xlo; }
    else if (dsel == 8) { hi = g_Vh; lo = g_Vl; }
    else {
        hi = g_Whi + (size_t)(dsel - 1) * 1048576;
        lo = g_Wlo + (size_t)(dsel - 1) * 1048576;
    }
    float4 v = *(const float4*)(s + 4 * (size_t)i);
    float vv[4] = {v.x, v.y, v.z, v.w};
    __nv_bfloat16 h[4], l[4];
#pragma unroll
    for (int j = 0; j < 4; ++j) {
        h[j] = __float2bfloat16(vv[j]);
        l[j] = __float2bfloat16(vv[j] - __bfloat162float(h[j]));
    }
    *(uint2*)(hi + 4 * (size_t)i) = *(uint2*)h;
    *(uint2*)(lo + 4 * (size_t)i) = *(uint2*)l;
}

// ---------------- HMMA split-bf16 GEMM: C = A @ W^T (EXACT round-10 body) ---
// 128x128 tile/CTA, BK=32, 8 warps (2m x 4n), single-buffer smem stride 40.
// fp32 outputs only — no split epilogue (register budget sits at the
// 2-CTA/SM edge; round-16 showed an added epilogue branch costs ~2x).
#define GST 40   // smem row stride in bf16

__global__ __launch_bounds__(256) void gemm_mma(int asel, int wsel, int csel,
                                                float* Cout) {
    __shared__ __nv_bfloat16 sAh[128 * GST];
    __shared__ __nv_bfloat16 sAl[128 * GST];
    __shared__ __nv_bfloat16 sWh[128 * GST];
    __shared__ __nv_bfloat16 sWl[128 * GST];

    const int tid = threadIdx.x, wid = tid >> 5, lid = tid & 31;
    const int wr = wid & 1, wc = wid >> 1;
    const int m0 = blockIdx.y * 128, n0 = blockIdx.x * 128;
    const int ws = (wsel < 0) ? (int)blockIdx.z : wsel;
    const int cs = (csel < 0) ? (int)blockIdx.z : csel;

    const __nv_bfloat16* Ah = asel ? g_Ahi : g_xhi;
    const __nv_bfloat16* Al = asel ? g_Alo : g_xlo;
    const __nv_bfloat16* Wh = g_Whi + (size_t)ws * 1048576;
    const __nv_bfloat16* Wl = g_Wlo + (size_t)ws * 1048576;
    float* C;
    switch (cs) {
        case 0: C = g_Q; break;
        case 1: C = g_K; break;
        case 2: C = g_V; break;
        default: C = Cout;
    }

    const uint32_t bAh = smem_u32(sAh), bAl = smem_u32(sAl);
    const uint32_t bWh = smem_u32(sWh), bWl = smem_u32(sWl);

    const int rowSelA = wr * 64 + (lid & 15);
    const int kSelA   = (lid >> 4) * 8;
    const int rowSelW = wc * 32 + ((lid >> 4) * 8) + (lid & 7);
    const int kSelW   = ((lid >> 3) & 1) * 8;

    float acc[4][4][4];
#pragma unroll
    for (int i = 0; i < 4; ++i)
#pragma unroll
        for (int j = 0; j < 4; ++j)
#pragma unroll
            for (int t = 0; t < 4; ++t) acc[i][j][t] = 0.f;

    for (int k0 = 0; k0 < 1024; k0 += 32) {
        __syncthreads();
#pragma unroll
        for (int p = 0; p < 2; ++p) {
            int c = tid + p * 256;
            int row = c >> 2, kc = (c & 3) * 8;
            int so = row * GST + kc;
            size_t ao = (size_t)(m0 + row) * 1024 + k0 + kc;
            size_t wo = (size_t)(n0 + row) * 1024 + k0 + kc;
            *(uint4*)(sAh + so) = *(const uint4*)(Ah + ao);
            *(uint4*)(sAl + so) = *(const uint4*)(Al + ao);
            *(uint4*)(sWh + so) = *(const uint4*)(Wh + wo);
            *(uint4*)(sWl + so) = *(const uint4*)(Wl + wo);
        }
        __syncthreads();

#pragma unroll
        for (int ks = 0; ks < 2; ++ks) {
            uint32_t bh[4][2], bl[4][2];
#pragma unroll
            for (int nt16 = 0; nt16 < 2; ++nt16) {
                uint32_t r[4];
                uint32_t off =
                    (uint32_t)((rowSelW + nt16 * 16) * GST + ks * 16 + kSelW) * 2;
                ldsm4(r, bWh + off);
                bh[nt16 * 2][0] = r[0]; bh[nt16 * 2][1] = r[1];
                bh[nt16 * 2 + 1][0] = r[2]; bh[nt16 * 2 + 1][1] = r[3];
                ldsm4(r, bWl + off);
                bl[nt16 * 2][0] = r[0]; bl[nt16 * 2][1] = r[1];
                bl[nt16 * 2 + 1][0] = r[2]; bl[nt16 * 2 + 1][1] = r[3];
            }
            uint32_t a[4][4];
#pragma unroll
            for (int mt = 0; mt < 4; ++mt)
                ldsm4(a[mt],
                      bAh + (uint32_t)((rowSelA + mt * 16) * GST + ks * 16 + kSelA) * 2);
#pragma unroll
            for (int mt = 0; mt < 4; ++mt)
#pragma unroll
                for (int nt = 0; nt < 4; ++nt) {
                    mma16816(acc[mt][nt], a[mt], bh[nt]);
                    mma16816(acc[mt][nt], a[mt], bl[nt]);
                }
#pragma unroll
            for (int mt = 0; mt < 4; ++mt)
                ldsm4(a[mt],
                      bAl + (uint32_t)((rowSelA + mt * 16) * GST + ks * 16 + kSelA) * 2);
#pragma unroll
            for (int mt = 0; mt < 4; ++mt)
#pragma unroll
                for (int nt = 0; nt < 4; ++nt)
                    mma16816(acc[mt][nt], a[mt], bh[nt]);
        }
    }

    const int g = lid >> 2, j2 = (lid & 3) * 2;
#pragma unroll
    for (int mt = 0; mt < 4; ++mt) {
        int row = m0 + wr * 64 + mt * 16 + g;
#pragma unroll
        for (int nt = 0; nt < 4; ++nt) {
            int col = n0 + wc * 32 + nt * 8 + j2;
            *(float2*)&C[(size_t)row * 1024 + col] =
                make_float2(acc[mt][nt][0], acc[mt][nt][1]);
            *(float2*)&C[(size_t)(row + 8) * 1024 + col] =
                make_float2(acc[mt][nt][2], acc[mt][nt][3]);
        }
    }
}

// ---------------- RoPE trig table (VERIFIED recipe: pow + cos/sin) ----------
// DO NOT switch to exp2/remainder/sincosf — failed 3/3 (rounds 3, 4, 15)
// with the 0.8156 degenerate-scores signature.
__global__ __launch_bounds__(256) void build_trig(const int* __restrict__ pos) {
    int idx = blockIdx.x * blockDim.x + threadIdx.x;
    if (idx >= S_ * 32) return;
    int s = idx >> 5;
    int i = idx & 31;
    double inv = pow(10000.0, -(double)(2 * i) / 64.0);
    double ang = (double)pos[s] * inv;
    g_cos[idx] = (float)cos(ang);
    g_sin[idx] = (float)sin(ang);
}

// ---------------- RoPE apply: fp32 Q/K -> rotated split bf16 ----------------
// Q scaled by 1/8 (softmax scale folded).
__global__ __launch_bounds__(256) void rope_apply() {
    int idx = blockIdx.x * blockDim.x + threadIdx.x;
    if (idx >= NTOK * (D_ / 2)) return;
    int i   = idx & 31;
    int r   = idx >> 5;
    int h   = r & 15;
    int tok = r >> 4;
    int s   = tok & (S_ - 1);
    float c  = g_cos[(s << 5) + i];
    float sn = g_sin[(s << 5) + i];
    size_t base = (size_t)tok * D_ + (size_t)h * DK_ + 2 * i;

    float2 q = *(float2*)&g_Q[base];
    float qx = (q.x * c - q.y * sn) * 0.125f;
    float qy = (q.x * sn + q.y * c) * 0.125f;
    uint32_t hi, lo;
    split2(qx, qy, hi, lo);
    *(uint32_t*)(g_Qh + base) = hi;
    *(uint32_t*)(g_Ql + base) = lo;

    float2 k = *(float2*)&g_K[base];
    float kx = k.x * c - k.y * sn;
    float ky = k.x * sn + k.y * c;
    split2(kx, ky, hi, lo);
    *(uint32_t*)(g_Kh + base) = hi;
    *(uint32_t*)(g_Kl + base) = lo;
}

// ---------------- fused flash attention (HMMA, split-bf16) ------------------
#define GSTF 72  // smem row stride (bf16)

__global__ __launch_bounds__(256) void flash_mma() {
    __shared__ __nv_bfloat16 sKh[64 * GSTF];
    __shared__ __nv_bfloat16 sKl[64 * GSTF];
    __shared__ __nv_bfloat16 sVh[64 * GSTF];
    __shared__ __nv_bfloat16 sVl[64 * GSTF];

    const int tid = threadIdx.x, wid = tid >> 5, lid = tid & 31;
    const int qt = 15 - (int)blockIdx.x;
    const int bh = blockIdx.y;
    const int b = bh >> 4, h = bh & 15;
    const size_t base = (size_t)b * S_ * D_ + (size_t)h * DK_;
    const int q0 = qt * 128;
    const int g = lid >> 2, j2 = (lid & 3) * 2;
    const int qrow0 = q0 + wid * 16 + g;

    uint32_t qh[4][4], ql[4][4];
#pragma unroll
    for (int ks = 0; ks < 4; ++ks) {
        size_t r0 = base + (size_t)qrow0 * D_ + ks * 16 + j2;
        size_t r1 = base + (size_t)(qrow0 + 8) * D_ + ks * 16 + j2;
        qh[ks][0] = *(const uint32_t*)(g_Qh + r0);
        qh[ks][1] = *(const uint32_t*)(g_Qh + r1);
        qh[ks][2] = *(const uint32_t*)(g_Qh + r0 + 8);
        qh[ks][3] = *(const uint32_t*)(g_Qh + r1 + 8);
        ql[ks][0] = *(const uint32_t*)(g_Ql + r0);
        ql[ks][1] = *(const uint32_t*)(g_Ql + r1);
        ql[ks][2] = *(const uint32_t*)(g_Ql + r0 + 8);
        ql[ks][3] = *(const uint32_t*)(g_Ql + r1 + 8);
    }

    float o[8][4];
#pragma unroll
    for (int nt = 0; nt < 8; ++nt)
#pragma unroll
        for (int t = 0; t < 4; ++t) o[nt][t] = 0.f;
    float m0 = -1e30f, m1 = -1e30f, l0 = 0.f, l1 = 0.f;

    const uint32_t bKh = smem_u32(sKh), bKl = smem_u32(sKl);
    const uint32_t bVh = smem_u32(sVh), bVl = smem_u32(sVl);
    const uint32_t selK =
        (uint32_t)((((lid >> 4) * 8) + (lid & 7)) * GSTF + ((lid >> 3) & 1) * 8) * 2;
    const uint32_t selV =
        (uint32_t)(((((lid >> 3) & 1) * 8) + (lid & 7)) * GSTF + (lid >> 4) * 8) * 2;

    const int nkt = 2 * qt + 2;
    for (int kt = 0; kt < nkt; ++kt) {
        const int k0 = kt * 64;
        __syncthreads();
#pragma unroll
        for (int p = 0; p < 2; ++p) {
            int c = tid + p * 256;
            int row = c >> 3, col8 = (c & 7) * 8;
            size_t go = base + (size_t)(k0 + row) * D_ + col8;
            int so = row * GSTF + col8;
            *(uint4*)(sKh + so) = *(const uint4*)(g_Kh + go);
            *(uint4*)(sKl + so) = *(const uint4*)(g_Kl + go);
            *(uint4*)(sVh + so) = *(const uint4*)(g_Vh + go);
            *(uint4*)(sVl + so) = *(const uint4*)(g_Vl + go);
        }
        __syncthreads();

        float s[8][4];
#pragma unroll
        for (int nt = 0; nt < 8; ++nt)
#pragma unroll
            for (int t = 0; t < 4; ++t) s[nt][t] = 0.f;

#pragma unroll
        for (int ks = 0; ks < 4; ++ks) {
            uint32_t kbh[8][2], kbl[8][2], r[4];
#pragma unroll
            for (int n16 = 0; n16 < 4; ++n16) {
                uint32_t off = selK + (uint32_t)((n16 * 16) * GSTF + ks * 16) * 2;
                ldsm4(r, bKh + off);
                kbh[2 * n16][0] = r[0]; kbh[2 * n16][1] = r[1];
                kbh[2 * n16 + 1][0] = r[2]; kbh[2 * n16 + 1][1] = r[3];
                ldsm4(r, bKl + off);
                kbl[2 * n16][0] = r[0]; kbl[2 * n16][1] = r[1];
                kbl[2 * n16 + 1][0] = r[2]; kbl[2 * n16 + 1][1] = r[3];
            }
#pragma unroll
            for (int nt = 0; nt < 8; ++nt) {
                mma16816(s[nt], qh[ks], kbh[nt]);
                mma16816(s[nt], ql[ks], kbh[nt]);
                mma16816(s[nt], qh[ks], kbl[nt]);
            }
        }

        if (k0 + 63 > q0 + wid * 16) {
#pragma unroll
            for (int nt = 0; nt < 8; ++nt) {
                int key = k0 + nt * 8 + j2;
                if (key > qrow0)         s[nt][0] = -1e30f;
                if (key + 1 > qrow0)     s[nt][1] = -1e30f;
                if (key > qrow0 + 8)     s[nt][2] = -1e30f;
                if (key + 1 > qrow0 + 8) s[nt][3] = -1e30f;
            }
        }

        float mx0 = -1e30f, mx1 = -1e30f;
#pragma unroll
        for (int nt = 0; nt < 8; ++nt) {
            mx0 = fmaxf(mx0, fmaxf(s[nt][0], s[nt][1]));
            mx1 = fmaxf(mx1, fmaxf(s[nt][2], s[nt][3]));
        }
        mx0 = fmaxf(mx0, __shfl_xor_sync(0xffffffffu, mx0, 1));
        mx0 = fmaxf(mx0, __shfl_xor_sync(0xffffffffu, mx0, 2));
        mx1 = fmaxf(mx1, __shfl_xor_sync(0xffffffffu, mx1, 1));
        mx1 = fmaxf(mx1, __shfl_xor_sync(0xffffffffu, mx1, 2));
        float mn0 = fmaxf(m0, mx0), mn1 = fmaxf(m1, mx1);
        float a0 = __expf(m0 - mn0), a1 = __expf(m1 - mn1);
        float sum0 = 0.f, sum1 = 0.f;
#pragma unroll
        for (int nt = 0; nt < 8; ++nt) {
            s[nt][0] = __expf(s[nt][0] - mn0);
            s[nt][1] = __expf(s[nt][1] - mn0);
            s[nt][2] = __expf(s[nt][2] - mn1);
            s[nt][3] = __expf(s[nt][3] - mn1);
            sum0 += s[nt][0] + s[nt][1];
            sum1 += s[nt][2] + s[nt][3];
        }
        sum0 += __shfl_xor_sync(0xffffffffu, sum0, 1);
        sum0 += __shfl_xor_sync(0xffffffffu, sum0, 2);
        sum1 += __shfl_xor_sync(0xffffffffu, sum1, 1);
        sum1 += __shfl_xor_sync(0xffffffffu, sum1, 2);
        l0 = l0 * a0 + sum0;
        l1 = l1 * a1 + sum1;
        m0 = mn0; m1 = mn1;
#pragma unroll
        for (int nt = 0; nt < 8; ++nt) {
            o[nt][0] *= a0; o[nt][1] *= a0;
            o[nt][2] *= a1; o[nt][3] *= a1;
        }

#pragma unroll
        for (int ks = 0; ks < 4; ++ks) {
            uint32_t ph[4], pl[4];
            split2(s[2 * ks][0], s[2 * ks][1], ph[0], pl[0]);
            split2(s[2 * ks][2], s[2 * ks][3], ph[1], pl[1]);
            split2(s[2 * ks + 1][0], s[2 * ks + 1][1], ph[2], pl[2]);
            split2(s[2 * ks + 1][2], s[2 * ks + 1][3], ph[3], pl[3]);

            uint32_t vbh[8][2], vbl[8][2], r[4];
#pragma unroll
            for (int n16 = 0; n16 < 4; ++n16) {
                uint32_t off = selV + (uint32_t)((ks * 16) * GSTF + n16 * 16) * 2;
                ldsm4t(r, bVh + off);
                vbh[2 * n16][0] = r[0]; vbh[2 * n16][1] = r[1];
                vbh[2 * n16 + 1][0] = r[2]; vbh[2 * n16 + 1][1] = r[3];
                ldsm4t(r, bVl + off);
                vbl[2 * n16][0] = r[0]; vbl[2 * n16][1] = r[1];
                vbl[2 * n16 + 1][0] = r[2]; vbl[2 * n16 + 1][1] = r[3];
            }
#pragma unroll
            for (int nt = 0; nt < 8; ++nt) {
                mma16816(o[nt], ph, vbh[nt]);
                mma16816(o[nt], pl, vbh[nt]);
                mma16816(o[nt], ph, vbl[nt]);
            }
        }
    }

    // Epilogue: normalize and write SPLIT bf16 directly to g_Ahi/g_Alo.
    const float i0 = 1.f / l0, i1 = 1.f / l1;
#pragma unroll
    for (int nt = 0; nt < 8; ++nt) {
        size_t r0 = base + (size_t)qrow0 * D_ + nt * 8 + j2;
        size_t r1 = base + (size_t)(qrow0 + 8) * D_ + nt * 8 + j2;
        uint32_t hi, lo;
        split2(o[nt][0] * i0, o[nt][1] * i0, hi, lo);
        *(uint32_t*)(g_Ahi + r0) = hi;
        *(uint32_t*)(g_Alo + r0) = lo;
        split2(o[nt][2] * i1, o[nt][3] * i1, hi, lo);
        *(uint32_t*)(g_Ahi + r1) = hi;
        *(uint32_t*)(g_Alo + r1) = lo;
    }
}

// ---------------- launch -----------------------------------------------------
extern "C" void kernel_launch(void* const* d_in, const int* in_sizes, int n_in,
                              void* d_out, int out_size) {
    int ix = 0, ipos = 1;
    int iw[4] = {2, 3, 4, 5};
    {
        int nw = 0, found_x = 0, found_p = 0, tmp[8];
        for (int i = 0; i < n_in && i < 8; ++i) {
            if (in_sizes[i] == S_) { ipos = i; found_p = 1; }
            else if (in_sizes[i] == NTOK * D_) { ix = i; found_x = 1; }
            else if (nw < 8) tmp[nw++] = i;
        }
        if (found_x && found_p && nw >= 4) {
            iw[0] = tmp[0]; iw[1] = tmp[1]; iw[2] = tmp[2]; iw[3] = tmp[3];
        }
    }

    const float* x  = (const float*)d_in[ix];
    const int* pos  = (const int*)d_in[ipos];
    const float* Wq = (const float*)d_in[iw[0]];
    const float* Wk = (const float*)d_in[iw[1]];
    const float* Wv = (const float*)d_in[iw[2]];
    const float* Wo = (const float*)d_in[iw[3]];
    float* out = (float*)d_out;

    const int nT = NTOK * D_ / 4;
    const int nW = 1048576 / 4;

    split_k<<<(nT + 255) / 256, 256>>>(x, 0, 0, nT);
    split_k<<<(nW + 255) / 256, 256>>>(Wq, 0, 1, nW);
    split_k<<<(nW + 255) / 256, 256>>>(Wk, 0, 2, nW);
    split_k<<<(nW + 255) / 256, 256>>>(Wv, 0, 3, nW);
    split_k<<<(nW + 255) / 256, 256>>>(Wo, 0, 4, nW);

    // QKV projections in one launch (fp32 outputs; exact round-10 kernel).
    dim3 gqkv(D_ / 128, NTOK / 128, 3);
    gemm_mma<<<gqkv, 256>>>(0, -1, -1, nullptr);

    build_trig<<<(S_ * 32 + 255) / 256, 256>>>(pos);
    rope_apply<<<(NTOK * (D_ / 2) + 255) / 256, 256>>>();  // -> Qh/Ql/Kh/Kl

    // Single V split pass (g_V fp32 -> Vh/Vl).
    split_k<<<(nT + 255) / 256, 256>>>(nullptr, 1, 8, nT);

    dim3 fg(S_ / 128, SBH);
    flash_mma<<<fg, 256>>>();                               // -> Ahi/Alo

    dim3 go(D_ / 128, NTOK / 128, 1);
    gemm_mma<<<go, 256>>>(1, 3, 3, out);
}